// round 15
// baseline (speedup 1.0000x reference)
#include <cuda_runtime.h>
#include <math.h>

// out[b,d] = iw[A-1,d] * (sum_a spw[a]*hs[b,idx[a],d]) / (sum_a spw[a])
//
// Anchors are always a prefix of {0,1,2,5} (A<=4); counts[a] = Fib-like of
// k = position - sp, k in [1,12].
//
// Launch geometry: grid = (D4/128, B), block = 128 threads (4 warps = one
// per SMSP, the measured scheduler optimum). x1 coarsening: each thread owns
// ONE float4 column -> only 9 data LDG.128 per thread (half of the x2
// variant), halving per-warp prologue issue count and per-SM L1tex traffic,
// with 16 blocks spread over 16 SMs.
//  - ALL load addresses position-independent -> single overlapped memory
//    round trip; `position` only gates scalar weights.
//  - MLP anchor-parallel per warp (lane = a*8+s -> 8 hidden units), 3x
//    shfl_xor reduce, fast softplus, broadcast-first branchless tail with
//    pre-scaled anchor weights.

__device__ __forceinline__ float fib_sel(int k) {
    // a(1)=1, a(2)=2, a(k)=a(k-1)+a(k-2); k clamped to [1,12]. Select tree.
    float lo  = (k <= 1) ? 1.f  : (k == 2) ? 2.f   : (k == 3) ? 3.f  : 5.f;
    float mid = (k == 5) ? 8.f  : (k == 6) ? 13.f  : (k == 7) ? 21.f : 34.f;
    float hi  = (k == 9) ? 55.f : (k == 10) ? 89.f : (k == 11) ? 144.f : 233.f;
    return (k <= 4) ? lo : (k <= 8) ? mid : hi;
}

__device__ __forceinline__ float softplus_fast(float x) {
    return fmaxf(x, 0.0f) + __logf(1.0f + __expf(-fabsf(x)));
}

// grid = (D4/128, B), block = 128.
__global__ void __launch_bounds__(128, 1)
fla_kernel_s16(const float* __restrict__ hs,
               const float* __restrict__ iw,
               const float* __restrict__ w1,
               const float* __restrict__ b1,
               const float* __restrict__ w2,
               const float* __restrict__ b2,
               const int* __restrict__ pos_p,
               float* __restrict__ out,
               int S, int D4) {
    const int d4 = (blockIdx.x << 7) + threadIdx.x;   // column 0..D4-1
    const int lane = threadIdx.x & 31;
    const int a  = lane >> 3;            // anchor group 0..3
    const int s  = lane & 7;             // hidden-slice 0..7

    // ---- loads: position first, then output-critical hs rows ----
    const int position = __ldg(pos_p);

    const float4* base = reinterpret_cast<const float4*>(hs) +
                         (size_t)blockIdx.y * S * D4 + d4;
    float4 z = make_float4(0.f, 0.f, 0.f, 0.f);
    float4 v0 = __ldg(base);
    float4 v1 = (1 < S) ? __ldg(base + D4) : z;
    float4 v2 = (2 < S) ? __ldg(base + 2 * D4) : z;
    float4 v3 = (5 < S) ? __ldg(base + 5 * D4) : z;

    // candidate interference rows (row = A-1, A in 1..4)
    const float4* iwv = reinterpret_cast<const float4*>(iw) + d4;
    float4 g0 = __ldg(iwv);
    float4 g1 = __ldg(iwv + D4);
    float4 g2 = __ldg(iwv + 2 * D4);
    float4 g3 = __ldg(iwv + 3 * D4);

    // MLP weight slices
    const float4* w1v = reinterpret_cast<const float4*>(w1);
    const float4* b1v = reinterpret_cast<const float4*>(b1);
    const float4* w2v = reinterpret_cast<const float4*>(w2);
    const float4 w1a = __ldg(&w1v[2 * s]);
    const float4 w1b = __ldg(&w1v[2 * s + 1]);
    const float4 b1a = __ldg(&b1v[2 * s]);
    const float4 b1b = __ldg(&b1v[2 * s + 1]);
    const float4 w2a = __ldg(&w2v[2 * s]);
    const float4 w2b = __ldg(&w2v[2 * s + 1]);
    const float  b2s = __ldg(b2);

    // ---- scalar chain (under load latency) ----
    const bool val0 = (position >= 1) && (position < 13);
    const bool val1 = val0 && (1 < position) && (1 < S);
    const bool val2 = val0 && (2 < position) && (2 < S);
    const bool val3 = val0 && (5 < position) && (5 < S);
    const int A = (int)val0 + (int)val1 + (int)val2 + (int)val3;

    const int my_sp = a + ((a == 3) ? 2 : 0);   // {0,1,2,5}
    int k = position - my_sp;
    k = (k < 1) ? 1 : (k > 12 ? 12 : k);
    const float c = fib_sel(k);

    float h0 = fmaxf(fmaf(c, w1a.x, b1a.x), 0.f);
    float h1 = fmaxf(fmaf(c, w1a.y, b1a.y), 0.f);
    float h2 = fmaxf(fmaf(c, w1a.z, b1a.z), 0.f);
    float h3 = fmaxf(fmaf(c, w1a.w, b1a.w), 0.f);
    float h4 = fmaxf(fmaf(c, w1b.x, b1b.x), 0.f);
    float h5 = fmaxf(fmaf(c, w1b.y, b1b.y), 0.f);
    float h6 = fmaxf(fmaf(c, w1b.z, b1b.z), 0.f);
    float h7 = fmaxf(fmaf(c, w1b.w, b1b.w), 0.f);
    float q0 = h0 * w2a.x + h1 * w2a.y;
    float q1 = h2 * w2a.z + h3 * w2a.w;
    float q2 = h4 * w2b.x + h5 * w2b.y;
    float q3 = h6 * w2b.z + h7 * w2b.w;
    float p  = (q0 + q1) + (q2 + q3);

    p += __shfl_xor_sync(0xffffffffu, p, 1);
    p += __shfl_xor_sync(0xffffffffu, p, 2);
    p += __shfl_xor_sync(0xffffffffu, p, 4);

    // masked softplus; A==0 -> all zero (branchless zero output below)
    const float spw = (a < A) ? softplus_fast(p + b2s) : 0.0f;

    // broadcast-first (one parallel shuffle level), then local sum + rcp
    float wa0 = __shfl_sync(0xffffffffu, spw, 0);
    float wa1 = __shfl_sync(0xffffffffu, spw, 8);
    float wa2 = __shfl_sync(0xffffffffu, spw, 16);
    float wa3 = __shfl_sync(0xffffffffu, spw, 24);
    const float ssum = (wa0 + wa1) + (wa2 + wa3);
    const float inv  = (ssum > 0.f) ? __frcp_rn(ssum) : 0.0f;   // A==0 -> 0
    wa0 *= inv; wa1 *= inv; wa2 *= inv; wa3 *= inv;  // pre-scale once

    const float4 g = (A == 1) ? g0 : (A == 2) ? g1 : (A == 3) ? g2 : g3;

    float4 acc;
    acc.x = wa0 * v0.x; acc.y = wa0 * v0.y; acc.z = wa0 * v0.z; acc.w = wa0 * v0.w;
    acc.x = fmaf(wa1, v1.x, acc.x); acc.y = fmaf(wa1, v1.y, acc.y);
    acc.z = fmaf(wa1, v1.z, acc.z); acc.w = fmaf(wa1, v1.w, acc.w);
    acc.x = fmaf(wa2, v2.x, acc.x); acc.y = fmaf(wa2, v2.y, acc.y);
    acc.z = fmaf(wa2, v2.z, acc.z); acc.w = fmaf(wa2, v2.w, acc.w);
    acc.x = fmaf(wa3, v3.x, acc.x); acc.y = fmaf(wa3, v3.y, acc.y);
    acc.z = fmaf(wa3, v3.z, acc.z); acc.w = fmaf(wa3, v3.w, acc.w);
    reinterpret_cast<float4*>(out)[(size_t)blockIdx.y * D4 + d4] =
        make_float4(acc.x * g.x, acc.y * g.y, acc.z * g.z, acc.w * g.w);
}

// Generic fallback (any D), not hit for this problem's shapes.
__global__ void fla_kernel_scalar(const float* __restrict__ hs,
                                  const float* __restrict__ iw,
                                  const float* __restrict__ w1,
                                  const float* __restrict__ b1,
                                  const float* __restrict__ w2,
                                  const float* __restrict__ b2,
                                  const int* __restrict__ pos_p,
                                  float* __restrict__ out,
                                  int B, int S, int D) {
    const int position = __ldg(pos_p);
    int A = 0;
    if (position >= 1 && position < 13) {
        A = (0 < position)
          + (1 < position && 1 < S)
          + (2 < position && 2 < S)
          + (5 < position && 5 < S);
    }
    const int total = B * D;
    const int tid = blockIdx.x * blockDim.x + threadIdx.x;
    if (A == 0) {
        for (int i = tid; i < total; i += gridDim.x * blockDim.x) out[i] = 0.0f;
        return;
    }
    float spw[4], ssum = 0.f;
    for (int t = 0; t < 4; t++) {
        int sp = t + ((t == 3) ? 2 : 0);
        if (t < A) {
            int k = position - sp;
            k = (k < 1) ? 1 : (k > 12 ? 12 : k);
            float cc = fib_sel(k);
            float acc = 0.f;
            for (int j = 0; j < 64; j++)
                acc = fmaf(fmaxf(fmaf(cc, w1[j], b1[j]), 0.f), w2[j], acc);
            spw[t] = softplus_fast(acc + b2[0]);
        } else spw[t] = 0.f;
        ssum += spw[t];
    }
    const float inv = 1.0f / ssum;
    const float* iwr = iw + (size_t)(A - 1) * D;
    for (int i = tid; i < total; i += gridDim.x * blockDim.x) {
        int b = i / D, d = i - b * D;
        float acc = 0.f;
        for (int t = 0; t < 4 && t < A; t++) {
            int sp = t + ((t == 3) ? 2 : 0);
            acc = fmaf(spw[t], hs[(size_t)b * S * D + (size_t)sp * D + d], acc);
        }
        out[i] = acc * iwr[d] * inv;
    }
}

extern "C" void kernel_launch(void* const* d_in, const int* in_sizes, int n_in,
                              void* d_out, int out_size) {
    const float* hs  = (const float*)d_in[0];  // (B, S, D)
    const float* iw  = (const float*)d_in[1];  // (10, D)
    const float* w1  = (const float*)d_in[2];  // (64, 1)
    const float* b1  = (const float*)d_in[3];  // (64,)
    const float* w2  = (const float*)d_in[4];  // (1, 64)
    const float* b2  = (const float*)d_in[5];  // (1,)
    const int*   pos = (const int*)d_in[6];    // scalar

    const int D = in_sizes[1] / 10;
    const int B = out_size / D;
    const int S = in_sizes[0] / (B * D);
    float* out = (float*)d_out;

    const int D4 = D >> 2;
    if ((D & 3) == 0 && D4 >= 128 && (D4 & 127) == 0) {
        dim3 grid(D4 >> 7, B);
        fla_kernel_s16<<<grid, 128>>>(hs, iw, w1, b1, w2, b2, pos, out, S, D4);
    } else {
        const int total = B * D;
        int blocks = (total + 255) / 256;
        if (blocks > 148) blocks = 148;
        fla_kernel_scalar<<<blocks, 256>>>(hs, iw, w1, b1, w2, b2, pos, out, B, S, D);
    }
}

// round 16
// speedup vs baseline: 1.0640x; 1.0640x over previous
#include <cuda_runtime.h>
#include <math.h>

// out[b,d] = iw[A-1,d] * (sum_a spw[a]*hs[b,idx[a],d]) / (sum_a spw[a])
//
// Anchors are always a prefix of {0,1,2,5} (A<=4); counts[a] = Fib-like of
// k = position - sp, k in [1,12].
//
// FINAL converged structure (best-measured across 15 rounds):
//  - grid(B) x block(D/8), x2 column coarsening: 4 warps = one per SMSP.
//    Measured launch-geometry optimum: 8w/x1=4.96, 4w/x2=4.74 (best),
//    4w/x1-16blk=5.12, 2w/x4=4.96, 1w/x1-64blk=5.28 us.
//  - ALL load addresses position-independent -> single overlapped memory
//    round trip; `position` only gates scalar weights (its cold LDG round
//    trip is semantically irreducible).
//  - hs loads issue FIRST (earliest LSU slots for output-critical data),
//    then iw candidate rows, then MLP weight slices.
//  - MLP anchor-parallel per warp (lane = a*8+s -> 8 hidden units), 3x
//    shfl_xor reduce, fast softplus, broadcast-first branchless tail with
//    pre-scaled anchor weights.

__device__ __forceinline__ float fib_sel(int k) {
    // a(1)=1, a(2)=2, a(k)=a(k-1)+a(k-2); k clamped to [1,12]. Select tree.
    float lo  = (k <= 1) ? 1.f  : (k == 2) ? 2.f   : (k == 3) ? 3.f  : 5.f;
    float mid = (k == 5) ? 8.f  : (k == 6) ? 13.f  : (k == 7) ? 21.f : 34.f;
    float hi  = (k == 9) ? 55.f : (k == 10) ? 89.f : (k == 11) ? 144.f : 233.f;
    return (k <= 4) ? lo : (k <= 8) ? mid : hi;
}

__device__ __forceinline__ float softplus_fast(float x) {
    return fmaxf(x, 0.0f) + __logf(1.0f + __expf(-fabsf(x)));
}

// grid = (B), block = (D/8); thread t covers float4 columns t and t+D8.
__global__ void __launch_bounds__(128, 1)
fla_kernel_x2(const float* __restrict__ hs,
              const float* __restrict__ iw,
              const float* __restrict__ w1,
              const float* __restrict__ b1,
              const float* __restrict__ w2,
              const float* __restrict__ b2,
              const int* __restrict__ pos_p,
              float* __restrict__ out,
              int S) {
    const int d4 = threadIdx.x;          // first column
    const int D8 = blockDim.x;           // = D4/2
    const int D4 = D8 * 2;
    const int lane = threadIdx.x & 31;
    const int a  = lane >> 3;            // anchor group 0..3
    const int s  = lane & 7;             // hidden-slice 0..7

    // ---- loads: position first, then output-critical hs rows ----
    const int position = __ldg(pos_p);

    const float4* base = reinterpret_cast<const float4*>(hs) +
                         (size_t)blockIdx.x * S * D4 + d4;
    float4 z = make_float4(0.f, 0.f, 0.f, 0.f);
    float4 v0a = __ldg(base),            v0b = __ldg(base + D8);
    float4 v1a = z, v1b = z, v2a = z, v2b = z, v3a = z, v3b = z;
    if (1 < S) { v1a = __ldg(base + D4);      v1b = __ldg(base + D4 + D8); }
    if (2 < S) { v2a = __ldg(base + 2 * D4);  v2b = __ldg(base + 2 * D4 + D8); }
    if (5 < S) { v3a = __ldg(base + 5 * D4);  v3b = __ldg(base + 5 * D4 + D8); }

    // candidate interference rows (row = A-1, A in 1..4)
    const float4* iwv = reinterpret_cast<const float4*>(iw) + d4;
    float4 g0a = __ldg(iwv),            g0b = __ldg(iwv + D8);
    float4 g1a = __ldg(iwv + D4),       g1b = __ldg(iwv + D4 + D8);
    float4 g2a = __ldg(iwv + 2 * D4),   g2b = __ldg(iwv + 2 * D4 + D8);
    float4 g3a = __ldg(iwv + 3 * D4),   g3b = __ldg(iwv + 3 * D4 + D8);

    // MLP weight slices
    const float4* w1v = reinterpret_cast<const float4*>(w1);
    const float4* b1v = reinterpret_cast<const float4*>(b1);
    const float4* w2v = reinterpret_cast<const float4*>(w2);
    const float4 w1a = __ldg(&w1v[2 * s]);
    const float4 w1b = __ldg(&w1v[2 * s + 1]);
    const float4 b1a = __ldg(&b1v[2 * s]);
    const float4 b1b = __ldg(&b1v[2 * s + 1]);
    const float4 w2a = __ldg(&w2v[2 * s]);
    const float4 w2b = __ldg(&w2v[2 * s + 1]);
    const float  b2s = __ldg(b2);

    // ---- scalar chain (under load latency) ----
    const bool val0 = (position >= 1) && (position < 13);
    const bool val1 = val0 && (1 < position) && (1 < S);
    const bool val2 = val0 && (2 < position) && (2 < S);
    const bool val3 = val0 && (5 < position) && (5 < S);
    const int A = (int)val0 + (int)val1 + (int)val2 + (int)val3;

    const int my_sp = a + ((a == 3) ? 2 : 0);   // {0,1,2,5}
    int k = position - my_sp;
    k = (k < 1) ? 1 : (k > 12 ? 12 : k);
    const float c = fib_sel(k);

    float h0 = fmaxf(fmaf(c, w1a.x, b1a.x), 0.f);
    float h1 = fmaxf(fmaf(c, w1a.y, b1a.y), 0.f);
    float h2 = fmaxf(fmaf(c, w1a.z, b1a.z), 0.f);
    float h3 = fmaxf(fmaf(c, w1a.w, b1a.w), 0.f);
    float h4 = fmaxf(fmaf(c, w1b.x, b1b.x), 0.f);
    float h5 = fmaxf(fmaf(c, w1b.y, b1b.y), 0.f);
    float h6 = fmaxf(fmaf(c, w1b.z, b1b.z), 0.f);
    float h7 = fmaxf(fmaf(c, w1b.w, b1b.w), 0.f);
    float q0 = h0 * w2a.x + h1 * w2a.y;
    float q1 = h2 * w2a.z + h3 * w2a.w;
    float q2 = h4 * w2b.x + h5 * w2b.y;
    float q3 = h6 * w2b.z + h7 * w2b.w;
    float p  = (q0 + q1) + (q2 + q3);

    p += __shfl_xor_sync(0xffffffffu, p, 1);
    p += __shfl_xor_sync(0xffffffffu, p, 2);
    p += __shfl_xor_sync(0xffffffffu, p, 4);

    // masked softplus; A==0 -> all zero (branchless zero output below)
    const float spw = (a < A) ? softplus_fast(p + b2s) : 0.0f;

    // broadcast-first (one parallel shuffle level), then local sum + rcp
    float wa0 = __shfl_sync(0xffffffffu, spw, 0);
    float wa1 = __shfl_sync(0xffffffffu, spw, 8);
    float wa2 = __shfl_sync(0xffffffffu, spw, 16);
    float wa3 = __shfl_sync(0xffffffffu, spw, 24);
    const float ssum = (wa0 + wa1) + (wa2 + wa3);
    const float inv  = (ssum > 0.f) ? __frcp_rn(ssum) : 0.0f;   // A==0 -> 0
    wa0 *= inv; wa1 *= inv; wa2 *= inv; wa3 *= inv;  // pre-scale once

    const float4 ga = (A == 1) ? g0a : (A == 2) ? g1a : (A == 3) ? g2a : g3a;
    const float4 gb = (A == 1) ? g0b : (A == 2) ? g1b : (A == 3) ? g2b : g3b;

    float4* outv = reinterpret_cast<float4*>(out) + (size_t)blockIdx.x * D4;

    {   // column d4
        float4 acc;
        acc.x = wa0 * v0a.x; acc.y = wa0 * v0a.y; acc.z = wa0 * v0a.z; acc.w = wa0 * v0a.w;
        acc.x = fmaf(wa1, v1a.x, acc.x); acc.y = fmaf(wa1, v1a.y, acc.y);
        acc.z = fmaf(wa1, v1a.z, acc.z); acc.w = fmaf(wa1, v1a.w, acc.w);
        acc.x = fmaf(wa2, v2a.x, acc.x); acc.y = fmaf(wa2, v2a.y, acc.y);
        acc.z = fmaf(wa2, v2a.z, acc.z); acc.w = fmaf(wa2, v2a.w, acc.w);
        acc.x = fmaf(wa3, v3a.x, acc.x); acc.y = fmaf(wa3, v3a.y, acc.y);
        acc.z = fmaf(wa3, v3a.z, acc.z); acc.w = fmaf(wa3, v3a.w, acc.w);
        outv[d4] = make_float4(acc.x * ga.x, acc.y * ga.y,
                               acc.z * ga.z, acc.w * ga.w);
    }
    {   // column d4 + D8
        float4 acc;
        acc.x = wa0 * v0b.x; acc.y = wa0 * v0b.y; acc.z = wa0 * v0b.z; acc.w = wa0 * v0b.w;
        acc.x = fmaf(wa1, v1b.x, acc.x); acc.y = fmaf(wa1, v1b.y, acc.y);
        acc.z = fmaf(wa1, v1b.z, acc.z); acc.w = fmaf(wa1, v1b.w, acc.w);
        acc.x = fmaf(wa2, v2b.x, acc.x); acc.y = fmaf(wa2, v2b.y, acc.y);
        acc.z = fmaf(wa2, v2b.z, acc.z); acc.w = fmaf(wa2, v2b.w, acc.w);
        acc.x = fmaf(wa3, v3b.x, acc.x); acc.y = fmaf(wa3, v3b.y, acc.y);
        acc.z = fmaf(wa3, v3b.z, acc.z); acc.w = fmaf(wa3, v3b.w, acc.w);
        outv[d4 + D8] = make_float4(acc.x * gb.x, acc.y * gb.y,
                                    acc.z * gb.z, acc.w * gb.w);
    }
}

// Generic fallback (any D), not hit for this problem's shapes.
__global__ void fla_kernel_scalar(const float* __restrict__ hs,
                                  const float* __restrict__ iw,
                                  const float* __restrict__ w1,
                                  const float* __restrict__ b1,
                                  const float* __restrict__ w2,
                                  const float* __restrict__ b2,
                                  const int* __restrict__ pos_p,
                                  float* __restrict__ out,
                                  int B, int S, int D) {
    const int position = __ldg(pos_p);
    int A = 0;
    if (position >= 1 && position < 13) {
        A = (0 < position)
          + (1 < position && 1 < S)
          + (2 < position && 2 < S)
          + (5 < position && 5 < S);
    }
    const int total = B * D;
    const int tid = blockIdx.x * blockDim.x + threadIdx.x;
    if (A == 0) {
        for (int i = tid; i < total; i += gridDim.x * blockDim.x) out[i] = 0.0f;
        return;
    }
    float spw[4], ssum = 0.f;
    for (int t = 0; t < 4; t++) {
        int sp = t + ((t == 3) ? 2 : 0);
        if (t < A) {
            int k = position - sp;
            k = (k < 1) ? 1 : (k > 12 ? 12 : k);
            float cc = fib_sel(k);
            float acc = 0.f;
            for (int j = 0; j < 64; j++)
                acc = fmaf(fmaxf(fmaf(cc, w1[j], b1[j]), 0.f), w2[j], acc);
            spw[t] = softplus_fast(acc + b2[0]);
        } else spw[t] = 0.f;
        ssum += spw[t];
    }
    const float inv = 1.0f / ssum;
    const float* iwr = iw + (size_t)(A - 1) * D;
    for (int i = tid; i < total; i += gridDim.x * blockDim.x) {
        int b = i / D, d = i - b * D;
        float acc = 0.f;
        for (int t = 0; t < 4 && t < A; t++) {
            int sp = t + ((t == 3) ? 2 : 0);
            acc = fmaf(spw[t], hs[(size_t)b * S * D + (size_t)sp * D + d], acc);
        }
        out[i] = acc * iwr[d] * inv;
    }
}

extern "C" void kernel_launch(void* const* d_in, const int* in_sizes, int n_in,
                              void* d_out, int out_size) {
    const float* hs  = (const float*)d_in[0];  // (B, S, D)
    const float* iw  = (const float*)d_in[1];  // (10, D)
    const float* w1  = (const float*)d_in[2];  // (64, 1)
    const float* b1  = (const float*)d_in[3];  // (64,)
    const float* w2  = (const float*)d_in[4];  // (1, 64)
    const float* b2  = (const float*)d_in[5];  // (1,)
    const int*   pos = (const int*)d_in[6];    // scalar

    const int D = in_sizes[1] / 10;
    const int B = out_size / D;
    const int S = in_sizes[0] / (B * D);
    float* out = (float*)d_out;

    const int D8 = D >> 3;
    if ((D & 7) == 0 && D8 >= 32 && D8 <= 1024 && (D8 & 31) == 0) {
        fla_kernel_x2<<<B, D8>>>(hs, iw, w1, b1, w2, b2, pos, out, S);
    } else {
        const int total = B * D;
        int blocks = (total + 255) / 256;
        if (blocks > 148) blocks = 148;
        fla_kernel_scalar<<<blocks, 256>>>(hs, iw, w1, b1, w2, b2, pos, out, B, S, D);
    }
}